// round 15
// baseline (speedup 1.0000x reference)
#include <cuda_runtime.h>
#include <cuda_fp16.h>
#include <cstdint>

#define B_   256
#define T_   256
#define EMB_ 384
#define H_   64

// fp16 weights [w][n][k]; Wq pre-scaled by 384^-.5*log2e.
__device__ __align__(16) __half g_wt[3][H_][EMB_];

#define SW128(o) ((o) ^ ((((uint32_t)(o)) >> 3) & 0x70))
#define QSCALE (0.05103103630798287f * 1.4426950408889634f)

__device__ __forceinline__ uint32_t smem_u32(const void* p) {
    uint32_t a;
    asm("{ .reg .u64 t; cvta.to.shared.u64 t, %1; cvt.u32.u64 %0, t; }"
        : "=r"(a) : "l"(p));
    return a;
}

__device__ __forceinline__ void ldsm4(uint32_t* r, uint32_t addr) {
    asm volatile("ldmatrix.sync.aligned.m8n8.x4.shared.b16 {%0,%1,%2,%3}, [%4];"
                 : "=r"(r[0]), "=r"(r[1]), "=r"(r[2]), "=r"(r[3]) : "r"(addr));
}

__device__ __forceinline__ void ldsm4t(uint32_t* r, uint32_t addr) {
    asm volatile("ldmatrix.sync.aligned.m8n8.x4.trans.shared.b16 {%0,%1,%2,%3}, [%4];"
                 : "=r"(r[0]), "=r"(r[1]), "=r"(r[2]), "=r"(r[3]) : "r"(addr));
}

__device__ __forceinline__ void mma16816h(float* d, const uint32_t* a,
                                          uint32_t b0, uint32_t b1) {
    asm volatile(
        "mma.sync.aligned.m16n8k16.row.col.f32.f16.f16.f32 "
        "{%0,%1,%2,%3}, {%4,%5,%6,%7}, {%8,%9}, {%0,%1,%2,%3};"
        : "+f"(d[0]), "+f"(d[1]), "+f"(d[2]), "+f"(d[3])
        : "r"(a[0]), "r"(a[1]), "r"(a[2]), "r"(a[3]), "r"(b0), "r"(b1));
}

__device__ __forceinline__ uint32_t pack_h2(float a, float b) {
    uint32_t r;
    asm("cvt.rn.f16x2.f32 %0, %1, %2;" : "=r"(r) : "f"(b), "f"(a));
    return r;
}

__device__ __forceinline__ void cp_async16(uint32_t saddr, const void* g) {
    asm volatile("cp.async.cg.shared.global [%0], [%1], 16;" :: "r"(saddr), "l"(g));
}
#define CP_COMMIT() asm volatile("cp.async.commit_group;" ::: "memory")
#define CP_WAIT0()  asm volatile("cp.async.wait_group 0;" ::: "memory")

// ---------------------------------------------------------------------------
// Kernel 0: W -> fp16, transposed to [n][k]; Wq pre-scaled. (validated)
// ---------------------------------------------------------------------------
__global__ void wconv(const float* __restrict__ Wq, const float* __restrict__ Wk,
                      const float* __restrict__ Wv) {
    int idx = blockIdx.x * 256 + threadIdx.x;
    if (idx >= 3 * H_ * (EMB_ / 4)) return;
    int w  = idx / (H_ * (EMB_ / 4));
    int r  = idx % (H_ * (EMB_ / 4));
    int n  = r / (EMB_ / 4);
    int k4 = (r % (EMB_ / 4)) * 4;
    const float* W = (w == 0) ? Wq : (w == 1) ? Wk : Wv;
    const float s = (w == 0) ? QSCALE : 1.0f;
    uint2 p;
    p.x = pack_h2(W[(k4 + 0) * H_ + n] * s, W[(k4 + 1) * H_ + n] * s);
    p.y = pack_h2(W[(k4 + 2) * H_ + n] * s, W[(k4 + 3) * H_ + n] * s);
    *(uint2*)&g_wt[w][n][k4] = p;
}

// ---------------------------------------------------------------------------
// Fused kernel: per-batch QKV projection + causal attention.
// 512 threads / 16 warps, 1 CTA per batch.
// smem: Q 0..32K | K 32K..64K | V 64K..96K | x stages 2x16K @98304 |
//       W stages 2x24K @131072  (176 KB)
// GEMM: single 12-chunk loop (2 M-passes merged), warp tile 32x48,
//       explicit ldsm->mma pipeline. SW128 applied at USE (never hoisted
//       across an add -- the XOR does not distribute over carries).
// ---------------------------------------------------------------------------
#define SM_X     98304
#define SM_WS    131072
#define SMEM_SZ  (SM_WS + 2*24576)

__device__ __forceinline__ void ldg_x(float4* xr, const float* __restrict__ xb,
                                      int k0, int tid) {
    #pragma unroll
    for (int it = 0; it < 4; it++) {
        int f = tid + it * 512;
        xr[it] = *(const float4*)&xb[(size_t)(f >> 4) * EMB_ + k0 + (f & 15) * 4];
    }
}

__device__ __forceinline__ void sts_x(const float4* xr, char* xs, int tid) {
    #pragma unroll
    for (int it = 0; it < 4; it++) {
        int f = tid + it * 512;
        uint32_t off = SW128((f >> 4) * 128 + (f & 15) * 8);
        uint2 p;
        p.x = pack_h2(xr[it].x, xr[it].y);
        p.y = pack_h2(xr[it].z, xr[it].w);
        *(uint2*)(xs + off) = p;
    }
}

__device__ __forceinline__ void cp_w(uint32_t wdst, int k0, int tid) {
    #pragma unroll
    for (int it = 0; it < 3; it++) {
        int f  = tid + it * 512;
        int w2 = f >> 9;
        int r  = f & 511;
        int n  = r >> 3;
        int q8 = r & 7;
        cp_async16(wdst + w2 * 8192 + SW128(n * 128 + q8 * 16),
                   &g_wt[w2][n][k0 + q8 * 8]);
    }
}

__global__ __launch_bounds__(512) void qkv_attn(const float* __restrict__ x,
                                                float* __restrict__ out)
{
    extern __shared__ char smem[];
    const uint32_t sb = smem_u32(smem);
    const int b    = blockIdx.x;
    const int tid  = threadIdx.x;
    const int wid  = tid >> 5;
    const int lane = tid & 31;

    const int lrow   = (lane & 7) + ((lane >> 3) & 1) * 8;
    const int a_colb = ((lane >> 4) & 1) * 16;
    const int b_n    = (lane >> 4) * 8 + (lane & 7);
    const int b_colb = ((lane >> 3) & 1) * 16;
    const int g      = lane >> 2;
    const int c4     = lane & 3;

    // ======================= Phase 1: QKV projection =======================
    const int wr_ = wid & 3;
    const int wc  = wid >> 2;
    const int r_base = wr_ * 32;
    const int c_base = wc * 48;

    // RAW (unswizzled) per-np B offsets + 8K-aligned tile bases (post-swizzle-safe)
    uint32_t b_raw[3], b_tile[3];
    #pragma unroll
    for (int np = 0; np < 3; np++) {
        const int colb = c_base + np * 16;
        b_tile[np] = (uint32_t)((colb >> 6) * 8192);
        b_raw[np]  = ((colb & 63) + b_n) * 128 + b_colb;
    }
    const uint32_t a_raw0 = (r_base + lrow)      * 128 + a_colb;
    const uint32_t a_raw1 = (r_base + 16 + lrow) * 128 + a_colb;

    float acc[2][6][4] = {};

    const float* xb0 = x + ((size_t)b * T_) * EMB_;
    float4 xr[4];
    ldg_x(xr, xb0, 0, tid);
    cp_w(sb + SM_WS, 0, tid);
    CP_COMMIT();

    #pragma unroll 1
    for (int c = 0; c < 12; c++) {
        const int st = c & 1;
        sts_x(xr, smem + SM_X + st * 16384, tid);
        CP_WAIT0();
        __syncthreads();

        if (c < 11) {
            const int c1 = c + 1;
            const float* xb = x + ((size_t)b * T_ + (c1 >= 6 ? 128 : 0)) * EMB_;
            ldg_x(xr, xb, (c1 % 6) * 64, tid);
            cp_w(sb + SM_WS + (st ^ 1) * 24576, (c1 % 6) * 64, tid);
            CP_COMMIT();
        }

        const uint32_t xs = sb + SM_X + st * 16384;
        const uint32_t wbase = sb + SM_WS + st * 24576;

        // Software-pipelined inner loop; SW128 applied to full offset at use.
        uint32_t a_cur[8], a_nxt[8], b_cur[4], b_nxt[4];
        ldsm4(a_cur,     xs + SW128(a_raw0));
        ldsm4(a_cur + 4, xs + SW128(a_raw1));
        ldsm4(b_cur, wbase + b_tile[0] + SW128(b_raw[0]));
        #pragma unroll
        for (int ks = 0; ks < 4; ks++) {
            #pragma unroll
            for (int np = 0; np < 3; np++) {
                if (np < 2) {
                    ldsm4(b_nxt, wbase + b_tile[np + 1] +
                                 SW128(b_raw[np + 1] + ks * 32));
                } else if (ks < 3) {
                    ldsm4(b_nxt, wbase + b_tile[0] +
                                 SW128(b_raw[0] + (ks + 1) * 32));
                    ldsm4(a_nxt,     xs + SW128(a_raw0 + (ks + 1) * 32));
                    ldsm4(a_nxt + 4, xs + SW128(a_raw1 + (ks + 1) * 32));
                }
                mma16816h(acc[0][2*np],   a_cur,     b_cur[0], b_cur[1]);
                mma16816h(acc[0][2*np+1], a_cur,     b_cur[2], b_cur[3]);
                mma16816h(acc[1][2*np],   a_cur + 4, b_cur[0], b_cur[1]);
                mma16816h(acc[1][2*np+1], a_cur + 4, b_cur[2], b_cur[3]);
                #pragma unroll
                for (int i = 0; i < 4; i++) b_cur[i] = b_nxt[i];
                if (np == 2) {
                    #pragma unroll
                    for (int i = 0; i < 8; i++) a_cur[i] = a_nxt[i];
                }
            }
        }

        // Pass epilogues: after chunk 5 (rows 0-127) and chunk 11 (rows 128-255)
        if (c == 5 || c == 11) {
            const int prow = (c == 5) ? 0 : 128;
            const int c2 = c4 * 2;
            #pragma unroll
            for (int rg = 0; rg < 2; rg++) {
                const int row = prow + r_base + rg * 16 + g;
                #pragma unroll
                for (int nt = 0; nt < 6; nt++) {
                    int col = c_base + nt * 8 + c2;
                    int w2  = col >> 6;
                    int n   = col & 63;
                    char* dst = smem + w2 * 32768;
                    *(uint32_t*)(dst + SW128(row * 128 + n * 2)) =
                        pack_h2(acc[rg][nt][0], acc[rg][nt][1]);
                    *(uint32_t*)(dst + SW128((row + 8) * 128 + n * 2)) =
                        pack_h2(acc[rg][nt][2], acc[rg][nt][3]);
                    acc[rg][nt][0] = 0.0f; acc[rg][nt][1] = 0.0f;
                    acc[rg][nt][2] = 0.0f; acc[rg][nt][3] = 0.0f;
                }
            }
        }
    }
    __syncthreads();

    // ======================= Phase 2: causal attention ======================
    const uint32_t qbase = sb;
    const uint32_t kbase = sb + 32768;
    const uint32_t vbase = sb + 65536;
    const int lcolh = a_colb;

    // SMSP-balanced tile map: 18 j-blocks per SMSP.
    const int tile = 4 * (wid >> 2) + ((wid & 3) ^ (wid >> 2));
    const int r0 = tile * 16;

    uint32_t qf[4][4];
    #pragma unroll
    for (int kc = 0; kc < 4; kc++)
        ldsm4(qf[kc], qbase + SW128((r0 + lrow) * 128 + kc * 32 + lcolh));

    float oacc[8][4] = {};
    float sum0 = 0.0f, sum1 = 0.0f;
    const int nb = (r0 + 47) >> 5;

    #pragma unroll 1
    for (int blk = 0; blk < nb; blk++) {
        const int s0 = blk * 32;
        float sacc[4][4] = {};

        #pragma unroll
        for (int kc = 0; kc < 4; kc++) {
            uint32_t bh[8];
            #pragma unroll
            for (int grp = 0; grp < 2; grp++) {
                uint32_t off = SW128((s0 + grp * 16 + lrow) * 128 + kc * 32 + lcolh);
                ldsm4(&bh[grp * 4], kbase + off);
            }
            #pragma unroll
            for (int nt = 0; nt < 4; nt++) {
                const int base = (nt >> 1) * 4;
                mma16816h(sacc[nt], qf[kc],
                          bh[base + (nt & 1)], bh[base + (nt & 1) + 2]);
            }
        }

        const bool last = (blk == nb - 1);
        float p[4][4];
        #pragma unroll
        for (int nt = 0; nt < 4; nt++) {
            #pragma unroll
            for (int rr = 0; rr < 4; rr++) {
                int j = s0 + nt * 8 + 2 * c4 + (rr & 1);
                int t = r0 + g + (rr >> 1) * 8;
                float e = (!last || j <= t) ? exp2f(sacc[nt][rr]) : 0.0f;
                p[nt][rr] = e;
                if (rr < 2) sum0 += e; else sum1 += e;
            }
        }

        uint32_t pf[2][4];
        #pragma unroll
        for (int kc2 = 0; kc2 < 2; kc2++) {
            const float* p0 = p[2 * kc2];
            const float* p1 = p[2 * kc2 + 1];
            pf[kc2][0] = pack_h2(p0[0], p0[1]);
            pf[kc2][1] = pack_h2(p0[2], p0[3]);
            pf[kc2][2] = pack_h2(p1[0], p1[1]);
            pf[kc2][3] = pack_h2(p1[2], p1[3]);
        }

        #pragma unroll
        for (int kc2 = 0; kc2 < 2; kc2++) {
            #pragma unroll
            for (int np = 0; np < 4; np++) {
                uint32_t off = SW128((s0 + kc2 * 16 + lrow) * 128 + np * 32 + lcolh);
                uint32_t vb[4];
                ldsm4t(vb, vbase + off);
                mma16816h(oacc[2*np],   pf[kc2], vb[0], vb[1]);
                mma16816h(oacc[2*np+1], pf[kc2], vb[2], vb[3]);
            }
        }
    }

    sum0 += __shfl_xor_sync(0xffffffffu, sum0, 1);
    sum0 += __shfl_xor_sync(0xffffffffu, sum0, 2);
    sum1 += __shfl_xor_sync(0xffffffffu, sum1, 1);
    sum1 += __shfl_xor_sync(0xffffffffu, sum1, 2);
    const float inv0 = 1.0f / sum0;
    const float inv1 = 1.0f / sum1;

    float* orow0 = out + ((size_t)b * T_ + r0 + g) * H_;
    float* orow1 = out + ((size_t)b * T_ + r0 + g + 8) * H_;
    #pragma unroll
    for (int nt = 0; nt < 8; nt++) {
        int n = nt * 8 + 2 * c4;
        *(float2*)&orow0[n] = make_float2(oacc[nt][0] * inv0, oacc[nt][1] * inv0);
        *(float2*)&orow1[n] = make_float2(oacc[nt][2] * inv1, oacc[nt][3] * inv1);
    }
}

// ---------------------------------------------------------------------------
extern "C" void kernel_launch(void* const* d_in, const int* in_sizes, int n_in,
                              void* d_out, int out_size)
{
    const float* x  = (const float*)d_in[0];
    const float* Wq = (const float*)d_in[1];
    const float* Wk = (const float*)d_in[2];
    const float* Wv = (const float*)d_in[3];
    float* out = (float*)d_out;
    (void)in_sizes; (void)n_in; (void)out_size;

    wconv<<<(3 * H_ * (EMB_ / 4) + 255) / 256, 256>>>(Wq, Wk, Wv);

    cudaFuncSetAttribute(qkv_attn, cudaFuncAttributeMaxDynamicSharedMemorySize, SMEM_SZ);
    qkv_attn<<<B_, 512, SMEM_SZ>>>(x, out);
}